// round 16
// baseline (speedup 1.0000x reference)
#include <cuda_runtime.h>
#include <cstdint>

// ---------------------------------------------------------------------------
// LocalGate: N=131072, D=1024, E=64, K=2, GATE_ST.
// FFMA2 GEMM, Eigen-two-panel fp32 numerics (bitwise == XLA:CPU reference):
//   logit = fl(chain(k<512) + chain(k>=512)).
// R16: TM=64, 64-thread CTAs, 7 CTAs/SM -> 2048 blocks over capacity 1036 =
// 1.98 waves (98.8% util) at the FFMA2 pipe floor. Thread tile (8tok x 8exp
// diagonal f32x2) and per-lane chain order identical to R12.
// ---------------------------------------------------------------------------

#define NTOK   131072
#define MDIM   1024
#define NEXP   64
#define NK     (NTOK * 2)
#define TM     64
#define THREADS 64
#define NBLK   (NTOK / TM)          // 2048
#define KC     16
#define NCH    (MDIM / KC)          // 64
#define HALF_CH 32                  // Eigen kc=512 panel boundary
#define AST    68                   // A row stride (words): 64 rows + 4 pad
#define BST    96                   // B row stride (words), 8 groups x 12
#define AWORDS (KC * AST)           // 1088
#define BWORDS (KC * BST)           // 1536
#define STGW   (AWORDS + BWORDS)    // 2624 words
#define STGB   (STGW * 4)           // 10496 B
#define NSTG   3
#define GK_SMEM (NSTG * STGB)       // 31488 -> 7 CTAs/SM (215KB)

#define SORT_BLOCKS 512
#define SORT_CHUNK  (NK / SORT_BLOCKS)  // 512 (= 4 gate blocks)

__device__ unsigned char g_flat[NK];
__device__ int   g_bh[SORT_BLOCKS * NEXP];
__device__ int   g_start[NEXP];
__device__ float g_wpad[NCH * KC * BST];   // W re-laid: [c][k][eg*12 + (e&7)]
__device__ float g_panelL[NTOK * NEXP];    // panel-L spill (33.5 MB)

__device__ __forceinline__ uint32_t smem_u32(const void* p) {
    uint32_t a;
    asm("{ .reg .u64 t; cvta.to.shared.u64 t, %1; cvt.u32.u64 %0, t; }" : "=r"(a) : "l"(p));
    return a;
}
__device__ __forceinline__ void cp16(uint32_t dst, const void* src) {
    asm volatile("cp.async.cg.shared.global [%0], [%1], 16;" :: "r"(dst), "l"(src) : "memory");
}
// packed fp32 FMA: per-lane IEEE rn FMA (bitwise == scalar FFMA chain)
__device__ __forceinline__ void ffma2(float2& d, const float2& a, const float2& b) {
    asm("fma.rn.f32x2 %0, %1, %2, %0;"
        : "+l"(*reinterpret_cast<unsigned long long*>(&d))
        : "l"(*reinterpret_cast<const unsigned long long*>(&a)),
          "l"(*reinterpret_cast<const unsigned long long*>(&b)));
}

// ---------------------------------------------------------------------------
__global__ void prep_kernel(const float* __restrict__ W)
{
    const int id = blockIdx.x * 256 + threadIdx.x;       // 65536 threads
    if (id < NCH * KC * NEXP) {
        const int c = id >> 10;          // / (KC*NEXP)
        const int k = (id >> 6) & 15;
        const int e = id & 63;
        g_wpad[c * (KC * BST) + k * BST + (e >> 3) * 12 + (e & 7)] =
            W[(size_t)e * MDIM + c * KC + k];
    }
    if (id < SORT_BLOCKS * NEXP) g_bh[id] = 0;
}

// ---------------------------------------------------------------------------
__global__ void __launch_bounds__(THREADS, 7)
gate_kernel(const float* __restrict__ X,
            float* __restrict__ probs_out, float* __restrict__ cw_out)
{
    extern __shared__ float smf[];
    __shared__ int h[NEXP];
    const uint32_t sbase = smem_u32(smf);
    const int t    = threadIdx.x;
    const int w    = t >> 5;             // warp 0..1
    const int lane = t & 31;
    const int tg   = lane >> 3;          // token group 0..3
    const int eg   = lane & 7;           // expert group 0..7
    const int tok0 = blockIdx.x * TM;
    h[t] = 0;                            // 64 threads cover NEXP

    // A staging: thread loads rows lr+16i (i=0..3), float4 at k4=lk4
    const int lr  = t >> 2;              // 0..15
    const int lk4 = t & 3;               // 0..3
    const float* xrow = X + (size_t)(tok0 + lr) * MDIM + lk4 * 4;

    float2 acc1[4][4], acc2[4][4];
    #pragma unroll
    for (int q = 0; q < 4; ++q)
        #pragma unroll
        for (int j = 0; j < 4; ++j) {
            acc1[q][j] = make_float2(0.f, 0.f);
            acc2[q][j] = make_float2(0.f, 0.f);
        }
    float4 pf[4];

    // B chunk copy: 1536 words = 384 x 16B, 6 cp16/thread
    auto cpB = [&](int c) {
        const int s = c % NSTG;
        const float* src = g_wpad + (size_t)c * (KC * BST);
        const uint32_t dst = sbase + s * STGB + AWORDS * 4;
        #pragma unroll
        for (int q = 0; q < 6; ++q)
            cp16(dst + (t + q * THREADS) * 16, src + (t + q * THREADS) * 4);
        asm volatile("cp.async.commit_group;" ::: "memory");
    };
    // A store (k-major, transposed from pf regs)
    auto stsA = [&](int c) {
        float* As = smf + (c % NSTG) * STGW;
        #pragma unroll
        for (int i = 0; i < 4; ++i) {
            const int row = lr + 16 * i;
            As[(lk4 * 4 + 0) * AST + row] = pf[i].x;
            As[(lk4 * 4 + 1) * AST + row] = pf[i].y;
            As[(lk4 * 4 + 2) * AST + row] = pf[i].z;
            As[(lk4 * 4 + 3) * AST + row] = pf[i].w;
        }
    };

    // prologue: A0 direct, A1 prefetched; B0,B1 in flight
    #pragma unroll
    for (int i = 0; i < 4; ++i) pf[i] = *(const float4*)(xrow + (size_t)i * 16 * MDIM);
    cpB(0); cpB(1);
    stsA(0);
    #pragma unroll
    for (int i = 0; i < 4; ++i) pf[i] = *(const float4*)(xrow + (size_t)i * 16 * MDIM + KC);
    asm volatile("cp.async.wait_group 1;" ::: "memory");
    __syncthreads();

    for (int c = 0; c < NCH; ++c) {
        const int s = c % NSTG;
        if (c + 2 < NCH) cpB(c + 2);

        const float* As = smf + s * STGW;
        const float* Bs = As + AWORDS;
        #pragma unroll
        for (int k = 0; k < KC; ++k) {
            const float* ak = As + k * AST + w * 32 + tg * 8;
            const float* bk = Bs + k * BST + eg * 12;
            float2 a[4], b[4], bs[4];
            #pragma unroll
            for (int q = 0; q < 4; ++q) a[q] = *(const float2*)(ak + 2 * q);
            #pragma unroll
            for (int j = 0; j < 4; ++j) b[j] = *(const float2*)(bk + 2 * j);
            #pragma unroll
            for (int j = 0; j < 4; ++j) bs[j] = make_float2(b[j].y, b[j].x);
            #pragma unroll
            for (int q = 0; q < 4; ++q)
                #pragma unroll
                for (int j = 0; j < 4; ++j) {
                    ffma2(acc1[q][j], a[q], b[j]);
                    ffma2(acc2[q][j], a[q], bs[j]);
                }
        }
        if (c + 1 < NCH) stsA(c + 1);
        if (c + 2 < NCH) {
            const float* xs = xrow + (c + 2) * KC;
            #pragma unroll
            for (int i = 0; i < 4; ++i) pf[i] = *(const float4*)(xs + (size_t)i * 16 * MDIM);
        }
        if (c + 2 < NCH) { asm volatile("cp.async.wait_group 1;" ::: "memory"); }
        else             { asm volatile("cp.async.wait_group 0;" ::: "memory"); }
        __syncthreads();

        if (c == HALF_CH - 1) {          // Eigen panel boundary: spill L, restart
            float* pl = g_panelL + ((size_t)(blockIdx.x * 2 + w)) * 2048 + lane * 4;
            #pragma unroll
            for (int q = 0; q < 4; ++q)
                #pragma unroll
                for (int jp = 0; jp < 2; ++jp) {
                    *(float4*)(pl + (q * 2 + jp) * 128) =
                        make_float4(acc1[q][2*jp].x, acc1[q][2*jp].y,
                                    acc1[q][2*jp+1].x, acc1[q][2*jp+1].y);
                    *(float4*)(pl + (8 + q * 2 + jp) * 128) =
                        make_float4(acc2[q][2*jp].x, acc2[q][2*jp].y,
                                    acc2[q][2*jp+1].x, acc2[q][2*jp+1].y);
                }
            #pragma unroll
            for (int q = 0; q < 4; ++q)
                #pragma unroll
                for (int j = 0; j < 4; ++j) {
                    acc1[q][j] = make_float2(0.f, 0.f);
                    acc2[q][j] = make_float2(0.f, 0.f);
                }
        }
    }

    // final = panelL + panelH (FADD, bitwise == Eigen C += panel updates)
    {
        const float* pl = g_panelL + ((size_t)(blockIdx.x * 2 + w)) * 2048 + lane * 4;
        #pragma unroll
        for (int q = 0; q < 4; ++q)
            #pragma unroll
            for (int jp = 0; jp < 2; ++jp) {
                float4 v1 = *(const float4*)(pl + (q * 2 + jp) * 128);
                float4 v2 = *(const float4*)(pl + (8 + q * 2 + jp) * 128);
                acc1[q][2*jp].x   += v1.x; acc1[q][2*jp].y   += v1.y;
                acc1[q][2*jp+1].x += v1.z; acc1[q][2*jp+1].y += v1.w;
                acc2[q][2*jp].x   += v2.x; acc2[q][2*jp].y   += v2.y;
                acc2[q][2*jp+1].x += v2.z; acc2[q][2*jp+1].y += v2.w;
            }
    }

    // ---- epilogue: per-token top-2 (exact) + softmax probs ----
    #pragma unroll
    for (int p = 0; p < 8; ++p) {
        const int q = p >> 1, r = p & 1;
        float lg[8];
        #pragma unroll
        for (int j = 0; j < 4; ++j) {
            lg[2*j]   = r ? acc2[q][j].y : acc1[q][j].x;
            lg[2*j+1] = r ? acc1[q][j].y : acc2[q][j].x;
        }
        float v1 = -1e30f, v2 = -1e30f; int i1 = 0, i2 = 0;
        #pragma unroll
        for (int m = 0; m < 8; ++m) {
            const float v = lg[m]; const int e = eg * 8 + m;
            if (v > v1)      { v2 = v1; i2 = i1; v1 = v; i1 = e; }
            else if (v > v2) { v2 = v;  i2 = e; }
        }
        #pragma unroll
        for (int msk = 1; msk < 8; msk <<= 1) {
            const float ov1 = __shfl_xor_sync(0xffffffffu, v1, msk);
            const int   oi1 = __shfl_xor_sync(0xffffffffu, i1, msk);
            const float ov2 = __shfl_xor_sync(0xffffffffu, v2, msk);
            const int   oi2 = __shfl_xor_sync(0xffffffffu, i2, msk);
            const bool g1 = (ov1 > v1) || (ov1 == v1 && oi1 < i1);
            if (g1) {
                const bool g2 = (v1 > ov2) || (v1 == ov2 && i1 < oi2);
                v2 = g2 ? v1 : ov2; i2 = g2 ? i1 : oi2;
                v1 = ov1; i1 = oi1;
            } else {
                const bool g2 = (ov1 > v2) || (ov1 == v2 && oi1 < i2);
                v2 = g2 ? ov1 : v2; i2 = g2 ? oi1 : i2;
            }
        }
        const int tok = tok0 + w * 32 + tg * 8 + p;
        if (eg == 0) {
            g_flat[(size_t)tok * 2]     = (unsigned char)i1;
            g_flat[(size_t)tok * 2 + 1] = (unsigned char)i2;
            atomicAdd(&h[i1], 1);
            atomicAdd(&h[i2], 1);
        }
        float ex[8], ssum = 0.f;
        #pragma unroll
        for (int m = 0; m < 8; ++m) { ex[m] = __expf(lg[m] - v1); ssum += ex[m]; }
        ssum += __shfl_xor_sync(0xffffffffu, ssum, 1);
        ssum += __shfl_xor_sync(0xffffffffu, ssum, 2);
        ssum += __shfl_xor_sync(0xffffffffu, ssum, 4);
        const float inv = 1.0f / ssum;
        float* pr = probs_out + (size_t)tok * NEXP + eg * 8;
        *(float4*)(pr)     = make_float4(ex[0]*inv, ex[1]*inv, ex[2]*inv, ex[3]*inv);
        *(float4*)(pr + 4) = make_float4(ex[4]*inv, ex[5]*inv, ex[6]*inv, ex[7]*inv);
    }
    cw_out[2 * tok0 + 2 * t]     = 1.0f;     // straight-through forward value
    cw_out[2 * tok0 + 2 * t + 1] = 1.0f;
    __syncthreads();
    atomicAdd(&g_bh[(blockIdx.x >> 2) * NEXP + t], h[t]);   // 4 blocks / chunk
}

// ---------------------------------------------------------------------------
// Counting sort: scan -> rank (hist fused into gate)
// ---------------------------------------------------------------------------
__global__ void scan_kernel(float* __restrict__ splits_out)
{
    __shared__ int tot[NEXP];
    const int w    = threadIdx.x >> 5;
    const int lane = threadIdx.x & 31;
    #pragma unroll
    for (int ee = 0; ee < 2; ++ee) {
        const int e = w * 2 + ee;
        int v[16], s = 0;
        #pragma unroll
        for (int i = 0; i < 16; ++i) v[i] = g_bh[(lane * 16 + i) * NEXP + e];
        #pragma unroll
        for (int i = 0; i < 16; ++i) { const int x = v[i]; v[i] = s; s += x; }
        int run = s;
        #pragma unroll
        for (int off = 1; off < 32; off <<= 1) {
            const int n = __shfl_up_sync(0xffffffffu, run, off);
            if (lane >= off) run += n;
        }
        const int excl = run - s;
        #pragma unroll
        for (int i = 0; i < 16; ++i) g_bh[(lane * 16 + i) * NEXP + e] = v[i] + excl;
        if (lane == 31) tot[e] = run;
    }
    __syncthreads();
    if (threadIdx.x < NEXP) splits_out[threadIdx.x] = (float)tot[threadIdx.x];
    if (threadIdx.x == 0) {
        int base = 0;
        for (int e = 0; e < NEXP; ++e) { g_start[e] = base; base += tot[e]; }
    }
}

__global__ void rank_kernel(float* __restrict__ to_out, float* __restrict__ ro_out)
{
    __shared__ int cnt[NEXP];
    const int lane = threadIdx.x;
    cnt[lane]      = g_start[lane]      + g_bh[blockIdx.x * NEXP + lane];
    cnt[lane + 32] = g_start[lane + 32] + g_bh[blockIdx.x * NEXP + lane + 32];
    __syncwarp();
    const int base = blockIdx.x * SORT_CHUNK;
    #pragma unroll
    for (int it = 0; it < SORT_CHUNK / 32; ++it) {
        const int i = base + it * 32 + lane;
        const int e = g_flat[i];
        const unsigned peers = __match_any_sync(0xffffffffu, e);
        const int leader = __ffs(peers) - 1;
        const int prior  = __popc(peers & ((1u << lane) - 1));
        int b = 0;
        if (lane == leader) b = atomicAdd(&cnt[e], __popc(peers));
        b = __shfl_sync(peers, b, leader);
        const int p = b + prior;
        to_out[p] = (float)(i >> 1);
        ro_out[i] = (float)p;
    }
}

// ---------------------------------------------------------------------------
extern "C" void kernel_launch(void* const* d_in, const int* in_sizes, int n_in,
                              void* d_out, int out_size)
{
    const float* X = (const float*)d_in[0];   // [131072, 1024]
    const float* W = (const float*)d_in[1];   // [64, 1024]
    float* out = (float*)d_out;

    float* TO  = out;
    float* RO  = out + NK;
    float* CW  = out + 2 * NK;
    float* SPL = out + 3 * NK;
    float* PR  = out + 3 * NK + NEXP;

    cudaFuncSetAttribute(gate_kernel, cudaFuncAttributeMaxDynamicSharedMemorySize, GK_SMEM);

    prep_kernel<<<256, 256>>>(W);
    gate_kernel<<<NBLK, THREADS, GK_SMEM>>>(X, PR, CW);
    scan_kernel<<<1, 1024>>>(SPL);
    rank_kernel<<<SORT_BLOCKS, 32>>>(TO, RO);
}